// round 14
// baseline (speedup 1.0000x reference)
#include <cuda_runtime.h>
#include <cuda_bf16.h>
#include <cstdint>

// Problem constants (shapes fixed by the dataset).
#define MAXN   50000
#define INC    128
#define OUTC   64
#define BN_EPS 1e-5f
#define CAP    64            // bucket capacity per node (in-degree ~Poisson(16))

// Fused tail configuration: 592 blocks * 256 threads, 4 blocks/SM on 148 SMs
// => all blocks co-resident, software grid barrier is deadlock-free.
#define TAIL_BLOCKS 592
#define TAIL_ITER   ((MAXN * OUTC + TAIL_BLOCKS * 256 - 1) / (TAIL_BLOCKS * 256))  // 22

// ---------------- scratch (device globals; no allocations allowed) ----------
__device__ float g_h[MAXN * OUTC];     // h_scaled = (x @ W) * dinv[row]
__device__ float g_agg[MAXN * OUTC];   // tanh(agg + bias)
__device__ int   g_cnt[MAXN];          // in-degree (excl. self loop) / scatter cursor
__device__ float g_dinv[MAXN];         // (1 + cnt)^{-1/2}
__device__ int   g_bucket[MAXN * CAP]; // src indices bucketed by dst
__device__ float g_sum[OUTC];          // BN channel sums
__device__ float g_sqsum[OUTC];        // BN channel sum of squares
__device__ int   g_count;              // tail barrier arrival counter
__device__ int   g_is64;               // edge_index dtype flag (1 = int64)

// ---------------- helpers ----------------------------------------------------
__device__ __forceinline__ float fast_tanh(float x) {
    float e = __expf(2.f * x);              // MUFU ex2
    return 1.f - __fdividef(2.f, e + 1.f);  // MUFU rcp
}
__device__ __forceinline__ uint32_t bfbits(float v) {
    return (uint32_t)__bfloat16_as_ushort(__float2bfloat16(v));
}
__device__ __forceinline__ float bfval(uint32_t b) {
    return __bfloat162float(__ushort_as_bfloat16((unsigned short)b));
}
__device__ __forceinline__ uint32_t pkhi(float a, float b) {
    return bfbits(a) | (bfbits(b) << 16);
}
__device__ __forceinline__ uint32_t pklo(float a, float b) {
    float ra = a - bfval(bfbits(a));
    float rb = b - bfval(bfbits(b));
    return bfbits(ra) | (bfbits(rb) << 16);
}
__device__ __forceinline__ void mma16816(float& d0, float& d1, float& d2, float& d3,
                                         uint32_t a0, uint32_t a1, uint32_t a2, uint32_t a3,
                                         uint32_t b0, uint32_t b1) {
    asm volatile("mma.sync.aligned.m16n8k16.row.col.f32.bf16.bf16.f32 "
                 "{%0,%1,%2,%3}, {%4,%5,%6,%7}, {%8,%9}, {%0,%1,%2,%3};"
                 : "+f"(d0), "+f"(d1), "+f"(d2), "+f"(d3)
                 : "r"(a0), "r"(a1), "r"(a2), "r"(a3), "r"(b0), "r"(b1));
}

// ---------------- kernel 1: init (zero cursors/sums) + dtype detect ----------
__global__ void k_init(const int* __restrict__ ei32, int E, int n) {
    int i = blockIdx.x * blockDim.x + threadIdx.x;
    if (i < n) g_cnt[i] = 0;
    if (blockIdx.x == 0) {
        __shared__ int flag;
        if (threadIdx.x == 0) flag = 0;
        __syncthreads();
        int checks = min(256, E);
        if ((int)threadIdx.x < checks) {
            // int64 data => every odd 32-bit word is a zero high word
            // (indices < 50000). int32 => these words are random indices.
            if (ei32[2 * threadIdx.x + 1] != 0) atomicOr(&flag, 1);
        }
        __syncthreads();
        if (threadIdx.x == 0) { g_is64 = (flag == 0) ? 1 : 0; g_count = 0; }
        if (threadIdx.x < OUTC) { g_sum[threadIdx.x] = 0.f; g_sqsum[threadIdx.x] = 0.f; }
    }
}

// ---------------- kernel 2: scatter edges into fixed-capacity buckets --------
__global__ __launch_bounds__(256) void k_scatter(const int* __restrict__ ei, int E) {
    int e = blockIdx.x * blockDim.x + threadIdx.x;
    if (e >= E) return;
    int s, d;
    if (g_is64) { s = ei[2 * e]; d = ei[2 * (E + e)]; }
    else        { s = ei[e];     d = ei[E + e]; }
    int pos = atomicAdd(&g_cnt[d], 1);
    if (pos < CAP) g_bucket[d * CAP + pos] = s;
}

// ---------------- kernel 3: dinv = (1 + cnt)^{-1/2} --------------------------
__global__ void k_dinv(int n) {
    int i = blockIdx.x * blockDim.x + threadIdx.x;
    if (i < n) g_dinv[i] = rsqrtf(1.f + (float)g_cnt[i]);
}

// ---------------- kernel 4: GEMM h_scaled = (x @ W) * dinv via HMMA ----------
// bf16 hi/lo split: h = xh@Wh + xh@Wl + xl@Wh, one fp32 accumulator set.
// 256 threads = 8 warps; warp w owns rows row0 + w*16 .. +15; full N=64.
// A fragments register double-buffered across the kc loop to hide DRAM latency.
// Epilogue scales by dinv[row] so k_agg needs no per-edge normalization.
__global__ __launch_bounds__(256) void k_gemm(const float* __restrict__ x,
                                              const float* __restrict__ W,
                                              int n) {
    __shared__ uint2 bhi[8 * 8 * 32];   // [kc][nt][lane]  16 KB
    __shared__ uint2 blo[8 * 8 * 32];   //                 16 KB

    const int tid  = threadIdx.x;
    const int wid  = tid >> 5;
    const int lane = tid & 31;
    const int row0 = blockIdx.x * 128;

    // ---- pack W fragments (2048 uint2 per array; 8 entries per thread)
    #pragma unroll
    for (int i = 0; i < 8; i++) {
        int e    = tid + i * 256;
        int kc   = e >> 8;
        int nt   = (e >> 5) & 7;
        int l    = e & 31;
        int nn   = nt * 8 + (l >> 2);
        int k0   = kc * 16 + (l & 3) * 2;
        float w00 = W[(size_t)k0 * OUTC + nn];
        float w01 = W[(size_t)(k0 + 1) * OUTC + nn];
        float w10 = W[(size_t)(k0 + 8) * OUTC + nn];
        float w11 = W[(size_t)(k0 + 9) * OUTC + nn];
        bhi[e] = make_uint2(pkhi(w00, w01), pkhi(w10, w11));
        blo[e] = make_uint2(pklo(w00, w01), pklo(w10, w11));
    }
    __syncthreads();

    float acc[8][4];
    #pragma unroll
    for (int t = 0; t < 8; t++)
        #pragma unroll
        for (int j = 0; j < 4; j++) acc[t][j] = 0.f;

    const int r0 = row0 + wid * 16 + (lane >> 2);   // fragment rows r0, r0+8
    const int r1 = r0 + 8;
    const bool v0 = r0 < n, v1 = r1 < n;
    const float* xr0 = x + (size_t)r0 * INC + (lane & 3) * 2;
    const float* xr1 = x + (size_t)r1 * INC + (lane & 3) * 2;

    const float2 z2 = make_float2(0.f, 0.f);
    float2 e0, e1, e2, e3;        // current chunk
    e0 = v0 ? *reinterpret_cast<const float2*>(xr0)     : z2;
    e1 = v1 ? *reinterpret_cast<const float2*>(xr1)     : z2;
    e2 = v0 ? *reinterpret_cast<const float2*>(xr0 + 8) : z2;
    e3 = v1 ? *reinterpret_cast<const float2*>(xr1 + 8) : z2;

    #pragma unroll
    for (int kc = 0; kc < 8; kc++) {
        // prefetch next chunk while computing this one
        float2 f0 = z2, f1 = z2, f2 = z2, f3 = z2;
        if (kc < 7) {
            f0 = v0 ? *reinterpret_cast<const float2*>(xr0 + (kc + 1) * 16)     : z2;
            f1 = v1 ? *reinterpret_cast<const float2*>(xr1 + (kc + 1) * 16)     : z2;
            f2 = v0 ? *reinterpret_cast<const float2*>(xr0 + (kc + 1) * 16 + 8) : z2;
            f3 = v1 ? *reinterpret_cast<const float2*>(xr1 + (kc + 1) * 16 + 8) : z2;
        }

        uint32_t ah0 = pkhi(e0.x, e0.y), al0 = pklo(e0.x, e0.y);
        uint32_t ah1 = pkhi(e1.x, e1.y), al1 = pklo(e1.x, e1.y);
        uint32_t ah2 = pkhi(e2.x, e2.y), al2 = pklo(e2.x, e2.y);
        uint32_t ah3 = pkhi(e3.x, e3.y), al3 = pklo(e3.x, e3.y);

        const uint2* bh = &bhi[(kc * 8) * 32 + lane];
        const uint2* bl = &blo[(kc * 8) * 32 + lane];
        #pragma unroll
        for (int nt = 0; nt < 8; nt++) {
            uint2 bH = bh[nt * 32];
            uint2 bL = bl[nt * 32];
            mma16816(acc[nt][0], acc[nt][1], acc[nt][2], acc[nt][3],
                     ah0, ah1, ah2, ah3, bH.x, bH.y);   // xh @ Wh
            mma16816(acc[nt][0], acc[nt][1], acc[nt][2], acc[nt][3],
                     ah0, ah1, ah2, ah3, bL.x, bL.y);   // xh @ Wl
            mma16816(acc[nt][0], acc[nt][1], acc[nt][2], acc[nt][3],
                     al0, al1, al2, al3, bH.x, bH.y);   // xl @ Wh
        }
        e0 = f0; e1 = f1; e2 = f2; e3 = f3;
    }

    // ---- epilogue: write h_scaled = acc * dinv[row]
    const int c0 = (lane & 3) * 2;
    const float da = v0 ? g_dinv[r0] : 0.f;
    const float db = v1 ? g_dinv[r1] : 0.f;
    #pragma unroll
    for (int nt = 0; nt < 8; nt++) {
        int c = nt * 8 + c0;
        if (v0)
            *reinterpret_cast<float2*>(g_h + (size_t)r0 * OUTC + c) =
                make_float2(acc[nt][0] * da, acc[nt][1] * da);
        if (v1)
            *reinterpret_cast<float2*>(g_h + (size_t)r1 * OUTC + c) =
                make_float2(acc[nt][2] * db, acc[nt][3] * db);
    }
}

// ---------------- kernel 5: bucket aggregate + bias + tanh (NO atomics) ------
// agg[d] = dinv[d] * (hs[d] + sum_j hs[s_j]);  hs = h_scaled.
// 16 lanes per dst node, one float4 per lane; inner loop is pure LDG + FADD.
__global__ __launch_bounds__(256) void k_agg(const float* __restrict__ bias, int n) {
    const int tid = threadIdx.x;
    const int grp = tid >> 4;
    const int sub = tid & 15;
    const int d = blockIdx.x * 16 + grp;
    if (d >= n) return;

    const float4* h4 = reinterpret_cast<const float4*>(g_h);
    const float4 bv = reinterpret_cast<const float4*>(bias)[sub];

    const int m = min(g_cnt[d], CAP);
    const float dinvd = g_dinv[d];

    float4 acc = h4[(size_t)d * 16 + sub];       // self loop (hs[d])

    const int* bkt = g_bucket + (size_t)d * CAP;
    int j = 0;
    for (; j + 3 < m; j += 4) {
        int s0 = bkt[j], s1 = bkt[j + 1], s2 = bkt[j + 2], s3 = bkt[j + 3];
        float4 v0 = __ldg(&h4[(size_t)s0 * 16 + sub]);
        float4 v1 = __ldg(&h4[(size_t)s1 * 16 + sub]);
        float4 v2 = __ldg(&h4[(size_t)s2 * 16 + sub]);
        float4 v3 = __ldg(&h4[(size_t)s3 * 16 + sub]);
        acc.x += v0.x + v1.x + v2.x + v3.x;
        acc.y += v0.y + v1.y + v2.y + v3.y;
        acc.z += v0.z + v1.z + v2.z + v3.z;
        acc.w += v0.w + v1.w + v2.w + v3.w;
    }
    for (; j < m; j++) {
        int s = bkt[j];
        float4 v = __ldg(&h4[(size_t)s * 16 + sub]);
        acc.x += v.x; acc.y += v.y; acc.z += v.z; acc.w += v.w;
    }

    float4 a;
    a.x = fast_tanh(acc.x * dinvd + bv.x);
    a.y = fast_tanh(acc.y * dinvd + bv.y);
    a.z = fast_tanh(acc.z * dinvd + bv.z);
    a.w = fast_tanh(acc.w * dinvd + bv.w);
    reinterpret_cast<float4*>(g_agg)[(size_t)d * 16 + sub] = a;
}

// ---------------- kernel 6: fused BN stats + normalize -----------------------
// g_agg already holds tanh'd activations; values stay in registers across a
// software grid barrier (all 592 blocks co-resident: __launch_bounds__(256,4)).
__global__ __launch_bounds__(256, 4) void k_tail(const float* __restrict__ gamma,
                                                 const float* __restrict__ beta,
                                                 float* __restrict__ out, int n) {
    const int total  = n * OUTC;
    const int stride = TAIL_BLOCKS * 256;          // multiple of 64
    const int tid    = threadIdx.x;
    const int c      = tid & 63;                   // channel fixed per thread
    const int idx0   = blockIdx.x * 256 + tid;

    float vals[TAIL_ITER];
    float s = 0.f, s2 = 0.f;
    #pragma unroll
    for (int t = 0; t < TAIL_ITER; t++) {
        int i = idx0 + t * stride;
        float a = 0.f;
        if (i < total) {
            a = g_agg[i];
            s  += a;
            s2 += a * a;
        }
        vals[t] = a;
    }

    __shared__ float sh[256], sh2[256];
    sh[tid]  = s;
    sh2[tid] = s2;
    __syncthreads();
    if (tid < 64) {
        float t1 = sh[tid]  + sh[tid + 64]  + sh[tid + 128]  + sh[tid + 192];
        float t2 = sh2[tid] + sh2[tid + 64] + sh2[tid + 128] + sh2[tid + 192];
        atomicAdd(&g_sum[c],   t1);
        atomicAdd(&g_sqsum[c], t2);
        __threadfence();
    }
    __syncthreads();

    // grid barrier: arrive, then spin until all blocks arrived
    if (tid == 0) {
        atomicAdd(&g_count, 1);
        while (*(volatile int*)&g_count < TAIL_BLOCKS) { }
    }
    __syncthreads();
    __threadfence();

    const float inv_n = 1.f / (float)n;
    float mean  = __ldcg(&g_sum[c])   * inv_n;
    float var   = __ldcg(&g_sqsum[c]) * inv_n - mean * mean;
    float scale = gamma[c] * rsqrtf(var + BN_EPS);
    float shift = beta[c] - mean * scale;
    #pragma unroll
    for (int t = 0; t < TAIL_ITER; t++) {
        int i = idx0 + t * stride;
        if (i < total) out[i] = vals[t] * scale + shift;
    }
}

// ---------------- launch -----------------------------------------------------
extern "C" void kernel_launch(void* const* d_in, const int* in_sizes, int n_in,
                              void* d_out, int out_size) {
    const float* x     = (const float*)d_in[0];
    const int*   ei    = (const int*)d_in[1];    // int32 view; dtype detected on device
    const float* W     = (const float*)d_in[2];
    const float* bias  = (const float*)d_in[3];
    const float* gamma = (const float*)d_in[4];
    const float* beta  = (const float*)d_in[5];
    float* out = (float*)d_out;

    const int n = in_sizes[0] / INC;             // 50000
    const int E = in_sizes[1] / 2;               // 800000 (same count for int32/int64 views)

    const int nblk = (n + 255) / 256;
    k_init<<<nblk, 256>>>(ei, E, n);
    k_scatter<<<(E + 255) / 256, 256>>>(ei, E);
    k_dinv<<<nblk, 256>>>(n);
    k_gemm<<<(n + 127) / 128, 256>>>(x, W, n);
    k_agg<<<(n + 15) / 16, 256>>>(bias, n);
    k_tail<<<TAIL_BLOCKS, 256>>>(gamma, beta, out, n);
}

// round 16
// speedup vs baseline: 1.0103x; 1.0103x over previous
#include <cuda_runtime.h>
#include <cuda_bf16.h>
#include <cstdint>

// Problem constants (shapes fixed by the dataset).
#define MAXN   50000
#define INC    128
#define OUTC   64
#define BN_EPS 1e-5f
#define CAP    64            // bucket capacity per node (in-degree ~Poisson(16))

// Fused agg+stats+normalize: 444 blocks * 256 threads, 3 blocks/SM on 148 SMs
// => all blocks co-resident, software grid barrier is deadlock-free.
#define AT_BLOCKS 444
#define AT_THREADS (AT_BLOCKS * 256)
#define AT_TASKS   (MAXN * 16)                     // (node, sub) pairs
#define AT_ITER    ((AT_TASKS + AT_THREADS - 1) / AT_THREADS)   // 8

// ---------------- scratch (device globals; no allocations allowed) ----------
__device__ float g_h[MAXN * OUTC];     // h_scaled = (x @ W) * dinv[row]
__device__ int   g_cnt[MAXN];          // in-degree (excl. self loop) / scatter cursor
__device__ int   g_bucket[MAXN * CAP]; // src indices bucketed by dst
__device__ float g_sum[OUTC];          // BN channel sums
__device__ float g_sqsum[OUTC];        // BN channel sum of squares
__device__ int   g_count;              // barrier arrival counter
__device__ int   g_is64;               // edge_index dtype flag (1 = int64)

// ---------------- helpers ----------------------------------------------------
__device__ __forceinline__ float fast_tanh(float x) {
    float e = __expf(2.f * x);              // MUFU ex2
    return 1.f - __fdividef(2.f, e + 1.f);  // MUFU rcp
}
__device__ __forceinline__ uint32_t bfbits(float v) {
    return (uint32_t)__bfloat16_as_ushort(__float2bfloat16(v));
}
__device__ __forceinline__ float bfval(uint32_t b) {
    return __bfloat162float(__ushort_as_bfloat16((unsigned short)b));
}
__device__ __forceinline__ uint32_t pkhi(float a, float b) {
    return bfbits(a) | (bfbits(b) << 16);
}
__device__ __forceinline__ uint32_t pklo(float a, float b) {
    float ra = a - bfval(bfbits(a));
    float rb = b - bfval(bfbits(b));
    return bfbits(ra) | (bfbits(rb) << 16);
}
__device__ __forceinline__ void mma16816(float& d0, float& d1, float& d2, float& d3,
                                         uint32_t a0, uint32_t a1, uint32_t a2, uint32_t a3,
                                         uint32_t b0, uint32_t b1) {
    asm volatile("mma.sync.aligned.m16n8k16.row.col.f32.bf16.bf16.f32 "
                 "{%0,%1,%2,%3}, {%4,%5,%6,%7}, {%8,%9}, {%0,%1,%2,%3};"
                 : "+f"(d0), "+f"(d1), "+f"(d2), "+f"(d3)
                 : "r"(a0), "r"(a1), "r"(a2), "r"(a3), "r"(b0), "r"(b1));
}

// ---------------- kernel 1: init (zero cursors/sums) + dtype detect ----------
__global__ void k_init(const int* __restrict__ ei32, int E, int n) {
    int i = blockIdx.x * blockDim.x + threadIdx.x;
    if (i < n) g_cnt[i] = 0;
    if (blockIdx.x == 0) {
        __shared__ int flag;
        if (threadIdx.x == 0) flag = 0;
        __syncthreads();
        int checks = min(256, E);
        if ((int)threadIdx.x < checks) {
            // int64 data => every odd 32-bit word is a zero high word
            // (indices < 50000). int32 => these words are random indices.
            if (ei32[2 * threadIdx.x + 1] != 0) atomicOr(&flag, 1);
        }
        __syncthreads();
        if (threadIdx.x == 0) { g_is64 = (flag == 0) ? 1 : 0; g_count = 0; }
        if (threadIdx.x < OUTC) { g_sum[threadIdx.x] = 0.f; g_sqsum[threadIdx.x] = 0.f; }
    }
}

// ---------------- kernel 2: scatter edges into fixed-capacity buckets --------
__global__ __launch_bounds__(256) void k_scatter(const int* __restrict__ ei, int E) {
    int e = blockIdx.x * blockDim.x + threadIdx.x;
    if (e >= E) return;
    int s, d;
    if (g_is64) { s = ei[2 * e]; d = ei[2 * (E + e)]; }
    else        { s = ei[e];     d = ei[E + e]; }
    int pos = atomicAdd(&g_cnt[d], 1);
    if (pos < CAP) g_bucket[d * CAP + pos] = s;
}

// ---------------- kernel 3: GEMM h_scaled = (x @ W) * dinv via HMMA ----------
// bf16 hi/lo split: h = xh@Wh + xh@Wl + xl@Wh, one fp32 accumulator set.
// 256 threads = 8 warps; warp w owns rows row0 + w*16 .. +15; full N=64.
// A fragments register double-buffered across the kc loop to hide DRAM latency.
// Epilogue scales by dinv[row] = rsqrt(1+cnt) so k_aggtail needs no per-edge norm.
__global__ __launch_bounds__(256) void k_gemm(const float* __restrict__ x,
                                              const float* __restrict__ W,
                                              int n) {
    __shared__ uint2 bhi[8 * 8 * 32];   // [kc][nt][lane]  16 KB
    __shared__ uint2 blo[8 * 8 * 32];   //                 16 KB

    const int tid  = threadIdx.x;
    const int wid  = tid >> 5;
    const int lane = tid & 31;
    const int row0 = blockIdx.x * 128;

    // ---- pack W fragments (2048 uint2 per array; 8 entries per thread)
    #pragma unroll
    for (int i = 0; i < 8; i++) {
        int e    = tid + i * 256;
        int kc   = e >> 8;
        int nt   = (e >> 5) & 7;
        int l    = e & 31;
        int nn   = nt * 8 + (l >> 2);
        int k0   = kc * 16 + (l & 3) * 2;
        float w00 = W[(size_t)k0 * OUTC + nn];
        float w01 = W[(size_t)(k0 + 1) * OUTC + nn];
        float w10 = W[(size_t)(k0 + 8) * OUTC + nn];
        float w11 = W[(size_t)(k0 + 9) * OUTC + nn];
        bhi[e] = make_uint2(pkhi(w00, w01), pkhi(w10, w11));
        blo[e] = make_uint2(pklo(w00, w01), pklo(w10, w11));
    }
    __syncthreads();

    float acc[8][4];
    #pragma unroll
    for (int t = 0; t < 8; t++)
        #pragma unroll
        for (int j = 0; j < 4; j++) acc[t][j] = 0.f;

    const int r0 = row0 + wid * 16 + (lane >> 2);   // fragment rows r0, r0+8
    const int r1 = r0 + 8;
    const bool v0 = r0 < n, v1 = r1 < n;
    const float* xr0 = x + (size_t)r0 * INC + (lane & 3) * 2;
    const float* xr1 = x + (size_t)r1 * INC + (lane & 3) * 2;

    const float2 z2 = make_float2(0.f, 0.f);
    float2 e0, e1, e2, e3;        // current chunk
    e0 = v0 ? *reinterpret_cast<const float2*>(xr0)     : z2;
    e1 = v1 ? *reinterpret_cast<const float2*>(xr1)     : z2;
    e2 = v0 ? *reinterpret_cast<const float2*>(xr0 + 8) : z2;
    e3 = v1 ? *reinterpret_cast<const float2*>(xr1 + 8) : z2;

    #pragma unroll
    for (int kc = 0; kc < 8; kc++) {
        // prefetch next chunk while computing this one
        float2 f0 = z2, f1 = z2, f2 = z2, f3 = z2;
        if (kc < 7) {
            f0 = v0 ? *reinterpret_cast<const float2*>(xr0 + (kc + 1) * 16)     : z2;
            f1 = v1 ? *reinterpret_cast<const float2*>(xr1 + (kc + 1) * 16)     : z2;
            f2 = v0 ? *reinterpret_cast<const float2*>(xr0 + (kc + 1) * 16 + 8) : z2;
            f3 = v1 ? *reinterpret_cast<const float2*>(xr1 + (kc + 1) * 16 + 8) : z2;
        }

        uint32_t ah0 = pkhi(e0.x, e0.y), al0 = pklo(e0.x, e0.y);
        uint32_t ah1 = pkhi(e1.x, e1.y), al1 = pklo(e1.x, e1.y);
        uint32_t ah2 = pkhi(e2.x, e2.y), al2 = pklo(e2.x, e2.y);
        uint32_t ah3 = pkhi(e3.x, e3.y), al3 = pklo(e3.x, e3.y);

        const uint2* bh = &bhi[(kc * 8) * 32 + lane];
        const uint2* bl = &blo[(kc * 8) * 32 + lane];
        #pragma unroll
        for (int nt = 0; nt < 8; nt++) {
            uint2 bH = bh[nt * 32];
            uint2 bL = bl[nt * 32];
            mma16816(acc[nt][0], acc[nt][1], acc[nt][2], acc[nt][3],
                     ah0, ah1, ah2, ah3, bH.x, bH.y);   // xh @ Wh
            mma16816(acc[nt][0], acc[nt][1], acc[nt][2], acc[nt][3],
                     ah0, ah1, ah2, ah3, bL.x, bL.y);   // xh @ Wl
            mma16816(acc[nt][0], acc[nt][1], acc[nt][2], acc[nt][3],
                     al0, al1, al2, al3, bH.x, bH.y);   // xl @ Wh
        }
        e0 = f0; e1 = f1; e2 = f2; e3 = f3;
    }

    // ---- epilogue: write h_scaled = acc * rsqrt(1 + cnt[row])
    const int c0 = (lane & 3) * 2;
    const float da = v0 ? rsqrtf(1.f + (float)g_cnt[r0]) : 0.f;
    const float db = v1 ? rsqrtf(1.f + (float)g_cnt[r1]) : 0.f;
    #pragma unroll
    for (int nt = 0; nt < 8; nt++) {
        int c = nt * 8 + c0;
        if (v0)
            *reinterpret_cast<float2*>(g_h + (size_t)r0 * OUTC + c) =
                make_float2(acc[nt][0] * da, acc[nt][1] * da);
        if (v1)
            *reinterpret_cast<float2*>(g_h + (size_t)r1 * OUTC + c) =
                make_float2(acc[nt][2] * db, acc[nt][3] * db);
    }
}

// ---------------- kernel 4: fused aggregate + tanh + BN stats + normalize ----
// agg[d] = dinv[d] * (hs[d] + sum_j hs[s_j]);  hs = h_scaled.
// Persistent: 444 blocks (3/SM, co-resident). Each thread owns AT_ITER
// (node, sub) tasks; tanh'd values stay in registers across the grid barrier,
// then get normalized and written straight to out. No intermediate buffer.
__global__ __launch_bounds__(256, 3) void k_aggtail(const float* __restrict__ bias,
                                                    const float* __restrict__ gamma,
                                                    const float* __restrict__ beta,
                                                    float* __restrict__ out, int n) {
    const int tid  = threadIdx.x;
    const int idx0 = blockIdx.x * 256 + tid;
    const int sub  = idx0 & 15;                    // constant across iterations
    const float4* h4 = reinterpret_cast<const float4*>(g_h);
    const float4 bv = reinterpret_cast<const float4*>(bias)[sub];

    float4 vals[AT_ITER];
    float4 s4 = make_float4(0.f, 0.f, 0.f, 0.f);
    float4 q4 = make_float4(0.f, 0.f, 0.f, 0.f);

    #pragma unroll
    for (int it = 0; it < AT_ITER; it++) {
        int t = idx0 + it * AT_THREADS;
        float4 a = make_float4(0.f, 0.f, 0.f, 0.f);
        if (t < AT_TASKS) {
            const int d = t >> 4;
            const int degd = g_cnt[d];
            const int m = min(degd, CAP);
            const float dinvd = rsqrtf(1.f + (float)degd);

            float4 acc = h4[(size_t)d * 16 + sub];      // self loop (hs[d])
            const int* bkt = g_bucket + (size_t)d * CAP;
            int j = 0;
            for (; j + 3 < m; j += 4) {
                int s0 = bkt[j], s1 = bkt[j + 1], s2 = bkt[j + 2], s3 = bkt[j + 3];
                float4 v0 = __ldg(&h4[(size_t)s0 * 16 + sub]);
                float4 v1 = __ldg(&h4[(size_t)s1 * 16 + sub]);
                float4 v2 = __ldg(&h4[(size_t)s2 * 16 + sub]);
                float4 v3 = __ldg(&h4[(size_t)s3 * 16 + sub]);
                acc.x += v0.x + v1.x + v2.x + v3.x;
                acc.y += v0.y + v1.y + v2.y + v3.y;
                acc.z += v0.z + v1.z + v2.z + v3.z;
                acc.w += v0.w + v1.w + v2.w + v3.w;
            }
            for (; j < m; j++) {
                int s = bkt[j];
                float4 v = __ldg(&h4[(size_t)s * 16 + sub]);
                acc.x += v.x; acc.y += v.y; acc.z += v.z; acc.w += v.w;
            }

            a.x = fast_tanh(acc.x * dinvd + bv.x);
            a.y = fast_tanh(acc.y * dinvd + bv.y);
            a.z = fast_tanh(acc.z * dinvd + bv.z);
            a.w = fast_tanh(acc.w * dinvd + bv.w);
            s4.x += a.x; s4.y += a.y; s4.z += a.z; s4.w += a.w;
            q4.x += a.x * a.x; q4.y += a.y * a.y; q4.z += a.z * a.z; q4.w += a.w * a.w;
        }
        vals[it] = a;
    }

    // block-level per-channel reduction (16 subs x float4 = 64 channels)
    __shared__ float4 shs[256], shq[256];
    shs[tid] = s4; shq[tid] = q4;
    __syncthreads();
    if (tid < 16) {
        float4 S = shs[tid], Q = shq[tid];
        #pragma unroll
        for (int g = 1; g < 16; g++) {
            float4 s = shs[g * 16 + tid], q = shq[g * 16 + tid];
            S.x += s.x; S.y += s.y; S.z += s.z; S.w += s.w;
            Q.x += q.x; Q.y += q.y; Q.z += q.z; Q.w += q.w;
        }
        atomicAdd(&g_sum[tid * 4 + 0], S.x);
        atomicAdd(&g_sum[tid * 4 + 1], S.y);
        atomicAdd(&g_sum[tid * 4 + 2], S.z);
        atomicAdd(&g_sum[tid * 4 + 3], S.w);
        atomicAdd(&g_sqsum[tid * 4 + 0], Q.x);
        atomicAdd(&g_sqsum[tid * 4 + 1], Q.y);
        atomicAdd(&g_sqsum[tid * 4 + 2], Q.z);
        atomicAdd(&g_sqsum[tid * 4 + 3], Q.w);
        __threadfence();
    }
    __syncthreads();

    // grid barrier: arrive, then spin until all blocks arrived
    if (tid == 0) {
        atomicAdd(&g_count, 1);
        while (*(volatile int*)&g_count < AT_BLOCKS) { }
    }
    __syncthreads();
    __threadfence();

    const float inv_n = 1.f / (float)n;
    const int c = sub * 4;
    float4 mean = make_float4(__ldcg(&g_sum[c])     * inv_n,
                              __ldcg(&g_sum[c + 1]) * inv_n,
                              __ldcg(&g_sum[c + 2]) * inv_n,
                              __ldcg(&g_sum[c + 3]) * inv_n);
    float4 var  = make_float4(__ldcg(&g_sqsum[c])     * inv_n - mean.x * mean.x,
                              __ldcg(&g_sqsum[c + 1]) * inv_n - mean.y * mean.y,
                              __ldcg(&g_sqsum[c + 2]) * inv_n - mean.z * mean.z,
                              __ldcg(&g_sqsum[c + 3]) * inv_n - mean.w * mean.w);
    const float4 gm = reinterpret_cast<const float4*>(gamma)[sub];
    const float4 bt = reinterpret_cast<const float4*>(beta)[sub];
    float4 scale = make_float4(gm.x * rsqrtf(var.x + BN_EPS),
                               gm.y * rsqrtf(var.y + BN_EPS),
                               gm.z * rsqrtf(var.z + BN_EPS),
                               gm.w * rsqrtf(var.w + BN_EPS));
    float4 shift = make_float4(bt.x - mean.x * scale.x,
                               bt.y - mean.y * scale.y,
                               bt.z - mean.z * scale.z,
                               bt.w - mean.w * scale.w);

    float4* out4 = reinterpret_cast<float4*>(out);
    #pragma unroll
    for (int it = 0; it < AT_ITER; it++) {
        int t = idx0 + it * AT_THREADS;
        if (t < AT_TASKS) {
            float4 a = vals[it];
            out4[t] = make_float4(a.x * scale.x + shift.x,
                                  a.y * scale.y + shift.y,
                                  a.z * scale.z + shift.z,
                                  a.w * scale.w + shift.w);
        }
    }
}

// ---------------- launch -----------------------------------------------------
extern "C" void kernel_launch(void* const* d_in, const int* in_sizes, int n_in,
                              void* d_out, int out_size) {
    const float* x     = (const float*)d_in[0];
    const int*   ei    = (const int*)d_in[1];    // int32 view; dtype detected on device
    const float* W     = (const float*)d_in[2];
    const float* bias  = (const float*)d_in[3];
    const float* gamma = (const float*)d_in[4];
    const float* beta  = (const float*)d_in[5];
    float* out = (float*)d_out;

    const int n = in_sizes[0] / INC;             // 50000
    const int E = in_sizes[1] / 2;               // 800000 (same count for int32/int64 views)

    const int nblk = (n + 255) / 256;
    k_init<<<nblk, 256>>>(ei, E, n);
    k_scatter<<<(E + 255) / 256, 256>>>(ei, E);
    k_gemm<<<(n + 127) / 128, 256>>>(x, W, n);
    k_aggtail<<<AT_BLOCKS, 256>>>(bias, gamma, beta, out, n);
}